// round 9
// baseline (speedup 1.0000x reference)
#include <cuda_runtime.h>
#include <cstdint>

#define H       30
#define NDP     15           // dim-pairs
#define BATCHN  16384
#define SEQ     784
#define NC      10
#define THREADS 128

typedef unsigned long long ull;

__device__ __forceinline__ ull ffma2(ull a, ull b, ull c) {
    ull d; asm("fma.rn.f32x2 %0, %1, %2, %3;" : "=l"(d) : "l"(a), "l"(b), "l"(c)); return d;
}
__device__ __forceinline__ ull pack2(float lo, float hi) {
    ull d; asm("mov.b64 %0, {%1, %2};" : "=l"(d) : "f"(lo), "f"(hi)); return d;
}
__device__ __forceinline__ void unpack2(ull v, float& lo, float& hi) {
    asm("mov.b64 {%0, %1}, %2;" : "=f"(lo), "=f"(hi) : "l"(v));
}
__device__ __forceinline__ float modrelu(float z, float b) {
    float m = fmaxf(fabsf(z) + b, 0.0f);
    unsigned r = __float_as_uint(m) | (__float_as_uint(z) & 0x80000000u);
    return __uint_as_float(r);
}

// One recurrence step for this thread's element, entirely in registers.
// wsm row dp (32 ulls): k=0..29 -> (W_hh[2dp][k], W_hh[2dp+1][k]),
//                       k=30    -> (W_ih[2dp],   W_ih[2dp+1]),
//                       k=31    -> (b_mod[2dp],  b_mod[2dp+1]).
__device__ __forceinline__ void rnn_step(float xt, ull* __restrict__ hd,
                                         const ulonglong2* __restrict__ w2base) {
    const ull xd = pack2(xt, xt);
    float hnew[2 * NDP];
#pragma unroll
    for (int dp = 0; dp < NDP; dp++) {
        const ulonglong2* w2 = w2base + dp * 16;
        const ulonglong2 v = w2[15];            // (x-weight pair, bias pair)
        ull acc = ffma2(v.x, xd, 0ull);
#pragma unroll
        for (int q = 0; q < 15; q++) {
            const ulonglong2 u = w2[q];          // k=2q, 2q+1 (uniform LDS.128)
            acc = ffma2(u.x, hd[2 * q],     acc);
            acc = ffma2(u.y, hd[2 * q + 1], acc);
        }
        float zl, zh; unpack2(acc, zl, zh);
        float bl_, bh_; unpack2(v.y, bl_, bh_);
        hnew[2 * dp]     = modrelu(zl, bl_);
        hnew[2 * dp + 1] = modrelu(zh, bh_);
    }
#pragma unroll
    for (int k = 0; k < H; k++) hd[k] = pack2(hnew[k], hnew[k]);
}

__global__ __launch_bounds__(THREADS, 1)
void rnn_modrelu_kernel(const float* __restrict__ inputs,   // [B, SEQ]
                        const float* __restrict__ W_ih,     // [H, 1]
                        const float* __restrict__ W_hh,     // [H, H]
                        const float* __restrict__ b_mod,    // [H]
                        const float* __restrict__ W_lin,    // [NC, H]
                        const float* __restrict__ b_lin,    // [NC]
                        float* __restrict__ out)            // [B, NC]
{
    __shared__ __align__(16) ull wsm[NDP * 32];

    const int tid = threadIdx.x;
    const int b   = blockIdx.x * THREADS + tid;   // this thread's batch element

    // stage packed weight table (once)
    for (int idx = tid; idx < NDP * 32; idx += THREADS) {
        const int dp = idx >> 5, k = idx & 31;
        const int r0 = 2 * dp, r1 = 2 * dp + 1;
        float lo, hi;
        if (k < H)       { lo = W_hh[r0 * H + k]; hi = W_hh[r1 * H + k]; }
        else if (k == H) { lo = W_ih[r0];         hi = W_ih[r1]; }
        else             { lo = b_mod[r0];        hi = b_mod[r1]; }
        wsm[dp * 32 + k] = pack2(lo, hi);
    }
    __syncthreads();

    ull hd[H];
#pragma unroll
    for (int k = 0; k < H; k++) hd[k] = 0ull;

    const ulonglong2* w2base = (const ulonglong2*)wsm;
    const float4* xp = (const float4*)(inputs + (size_t)b * SEQ);

    // 784 steps = 98 chunks of 8 floats; double-buffered LDG.128 prefetch.
    float4 xa0 = xp[0], xa1 = xp[1];
    float4 xb0, xb1;

#pragma unroll 1
    for (int c = 0; c < 98; c += 2) {
        // prefetch chunk c+1 (always exists: c <= 96 -> chunk 97)
        xb0 = xp[2 * c + 2];
        xb1 = xp[2 * c + 3];

        rnn_step(xa0.x, hd, w2base);
        rnn_step(xa0.y, hd, w2base);
        rnn_step(xa0.z, hd, w2base);
        rnn_step(xa0.w, hd, w2base);
        rnn_step(xa1.x, hd, w2base);
        rnn_step(xa1.y, hd, w2base);
        rnn_step(xa1.z, hd, w2base);
        rnn_step(xa1.w, hd, w2base);

        if (c + 2 < 98) {                       // prefetch chunk c+2
            xa0 = xp[2 * c + 4];
            xa1 = xp[2 * c + 5];
        }

        rnn_step(xb0.x, hd, w2base);
        rnn_step(xb0.y, hd, w2base);
        rnn_step(xb0.z, hd, w2base);
        rnn_step(xb0.w, hd, w2base);
        rnn_step(xb1.x, hd, w2base);
        rnn_step(xb1.y, hd, w2base);
        rnn_step(xb1.z, hd, w2base);
        rnn_step(xb1.w, hd, w2base);
    }

    // final linear: out[b, c] = W_lin[c,:] . h + b_lin[c]
    float h[H];
#pragma unroll
    for (int k = 0; k < H; k++) {
        float lo, hi; unpack2(hd[k], lo, hi);
        h[k] = lo;
    }
#pragma unroll
    for (int c = 0; c < NC; c++) {
        float s = b_lin[c];
#pragma unroll
        for (int k = 0; k < H; k++)
            s = fmaf(W_lin[c * H + k], h[k], s);
        out[(size_t)b * NC + c] = s;
    }
}

extern "C" void kernel_launch(void* const* d_in, const int* in_sizes, int n_in,
                              void* d_out, int out_size) {
    const float* inputs = (const float*)d_in[0];
    const float* W_ih   = (const float*)d_in[1];
    const float* W_hh   = (const float*)d_in[2];
    const float* b_mod  = (const float*)d_in[3];
    const float* W_lin  = (const float*)d_in[4];
    const float* b_lin  = (const float*)d_in[5];
    float* out = (float*)d_out;

    rnn_modrelu_kernel<<<BATCHN / THREADS, THREADS>>>(inputs, W_ih, W_hh, b_mod,
                                                      W_lin, b_lin, out);
}

// round 13
// speedup vs baseline: 1.4319x; 1.4319x over previous
#include <cuda_runtime.h>
#include <cstdint>

#define H       30
#define BATCHN  16384
#define SEQ     784
#define NC      10
#define THREADS 128
#define TCH     28          // 784 = 28 * 28

typedef unsigned long long ull;

__device__ __forceinline__ ull ffma2(ull a, ull b, ull c) {
    ull d; asm("fma.rn.f32x2 %0, %1, %2, %3;" : "=l"(d) : "l"(a), "l"(b), "l"(c)); return d;
}
__device__ __forceinline__ ull pack2(float lo, float hi) {
    ull d; asm("mov.b64 %0, {%1, %2};" : "=l"(d) : "f"(lo), "f"(hi)); return d;
}
__device__ __forceinline__ void unpack2(ull v, float& lo, float& hi) {
    asm("mov.b64 {%0, %1}, %2;" : "=f"(lo), "=f"(hi) : "l"(v));
}
__device__ __forceinline__ float modrelu(float z, float b) {
    float m = fmaxf(fabsf(z) + b, 0.0f);
    unsigned r = __float_as_uint(m) | (__float_as_uint(z) & 0x80000000u);
    return __uint_as_float(r);
}

// Weight table in smem: per output dim d, 16 ulls (8 LDS.128):
//   ull q (q=0..14): (W_hh[d][2q], W_hh[d][2q+1])
//   ull 15:          (W_ih[d],     b_mod[d])
// h lives in registers PACKED: hp[q] = (h_2q, h_2q+1), q=0..14.

__global__ __launch_bounds__(THREADS)
void rnn_modrelu_kernel(const float* __restrict__ inputs,   // [B, SEQ]
                        const float* __restrict__ W_ih,     // [H, 1]
                        const float* __restrict__ W_hh,     // [H, H]
                        const float* __restrict__ b_mod,    // [H]
                        const float* __restrict__ W_lin,    // [NC, H]
                        const float* __restrict__ b_lin,    // [NC]
                        float* __restrict__ out)            // [B, NC]
{
    __shared__ __align__(16) ull   wsm[H * 16];        // 3840 B
    __shared__ __align__(16) float xs[TCH * THREADS];  // 14336 B

    const int tid = threadIdx.x;
    const int b   = blockIdx.x * THREADS + tid;        // this thread's element
    const int b0  = blockIdx.x * THREADS;

    // ---- build weight table (once) ----
    for (int idx = tid; idx < H * 16; idx += THREADS) {
        const int d = idx >> 4, k = idx & 15;
        float lo, hi;
        if (k < 15) { lo = W_hh[d * H + 2 * k]; hi = W_hh[d * H + 2 * k + 1]; }
        else        { lo = W_ih[d];             hi = b_mod[d]; }
        wsm[d * 16 + k] = pack2(lo, hi);
    }
    __syncthreads();

    ull hp[15];
#pragma unroll
    for (int q = 0; q < 15; q++) hp[q] = 0ull;

    const ulonglong2* wtab = (const ulonglong2*)wsm;   // 8 u2 per dim row

    for (int ch = 0; ch < TCH; ch++) {
        // ---- stage 28 steps of x for all 128 rows ----
        for (int idx = tid; idx < TCH * THREADS; idx += THREADS) {
            const int r = idx / TCH;          // local row
            const int i = idx - r * TCH;      // time within chunk
            xs[i * THREADS + r] = inputs[(size_t)(b0 + r) * SEQ + ch * TCH + i];
        }
        __syncthreads();

#pragma unroll 1
        for (int i = 0; i < TCH; i++) {
            const float x = xs[i * THREADS + tid];

            ull hnext[15];
#pragma unroll
            for (int p = 0; p < 15; p++) {
                const int d0 = 2 * p, d1 = 2 * p + 1;
                const ulonglong2* r0 = wtab + d0 * 8;
                const ulonglong2* r1 = wtab + d1 * 8;

                // two 15-deep partial-product chains (dims d0, d1)
                ull a = 0ull, c = 0ull;
#pragma unroll
                for (int q = 0; q < 7; q++) {
                    const ulonglong2 u0 = r0[q];
                    const ulonglong2 u1 = r1[q];
                    a = ffma2(u0.x, hp[2 * q],     a);
                    c = ffma2(u1.x, hp[2 * q],     c);
                    a = ffma2(u0.y, hp[2 * q + 1], a);
                    c = ffma2(u1.y, hp[2 * q + 1], c);
                }
                const ulonglong2 t0 = r0[7];   // (.x = k-pair 14, .y = (wih, b))
                const ulonglong2 t1 = r1[7];
                a = ffma2(t0.x, hp[14], a);
                c = ffma2(t1.x, hp[14], c);

                float al, ah, cl, chh;
                unpack2(a, al, ah);
                unpack2(c, cl, chh);
                float w0, bb0, w1, bb1;
                unpack2(t0.y, w0, bb0);
                unpack2(t1.y, w1, bb1);

                const float z0 = fmaf(x, w0, al + ah);
                const float z1 = fmaf(x, w1, cl + chh);
                hnext[p] = pack2(modrelu(z0, bb0), modrelu(z1, bb1));
            }
#pragma unroll
            for (int q = 0; q < 15; q++) hp[q] = hnext[q];
        }
        __syncthreads();   // xs reuse barrier for next chunk
    }

    // ---- final linear ----
    float h[H];
#pragma unroll
    for (int q = 0; q < 15; q++) unpack2(hp[q], h[2 * q], h[2 * q + 1]);
#pragma unroll
    for (int c = 0; c < NC; c++) {
        float s = b_lin[c];
#pragma unroll
        for (int k = 0; k < H; k++)
            s = fmaf(W_lin[c * H + k], h[k], s);
        out[(size_t)b * NC + c] = s;
    }
}

extern "C" void kernel_launch(void* const* d_in, const int* in_sizes, int n_in,
                              void* d_out, int out_size) {
    const float* inputs = (const float*)d_in[0];
    const float* W_ih   = (const float*)d_in[1];
    const float* W_hh   = (const float*)d_in[2];
    const float* b_mod  = (const float*)d_in[3];
    const float* W_lin  = (const float*)d_in[4];
    const float* b_lin  = (const float*)d_in[5];
    float* out = (float*)d_out;

    rnn_modrelu_kernel<<<BATCHN / THREADS, THREADS>>>(inputs, W_ih, W_hh, b_mod,
                                                      W_lin, b_lin, out);
}

// round 14
// speedup vs baseline: 4.7818x; 3.3394x over previous
#include <cuda_runtime.h>
#include <cstdint>

#define H       30
#define BATCHN  16384
#define SEQ     784
#define NC      10
#define THREADS 128
#define TCH     28          // 784 = 28 * 28
#define NDP     15          // dim pairs

typedef unsigned long long ull;

__device__ __forceinline__ ull ffma2(ull a, ull b, ull c) {
    ull d; asm("fma.rn.f32x2 %0, %1, %2, %3;" : "=l"(d) : "l"(a), "l"(b), "l"(c)); return d;
}
__device__ __forceinline__ ull pack2(float lo, float hi) {
    ull d; asm("mov.b64 %0, {%1, %2};" : "=l"(d) : "f"(lo), "f"(hi)); return d;
}
__device__ __forceinline__ void unpack2(ull v, float& lo, float& hi) {
    asm("mov.b64 {%0, %1}, %2;" : "=f"(lo), "=f"(hi) : "l"(v));
}
__device__ __forceinline__ float modrelu(float z, float b) {
    float m = fmaxf(fabsf(z) + b, 0.0f);
    unsigned r = __float_as_uint(m) | (__float_as_uint(z) & 0x80000000u);
    return __uint_as_float(r);
}

// Weight table in smem, per output dim d: 16 ulls (8 LDS.128 per row):
//   ull q (q=0..14): (W_hh[d][2q], W_hh[d][2q+1]);  ull 15: (W_ih[d], b_mod[d])
// h lives in registers packed: hp[q] = (h_2q, h_2q+1).

__global__ __launch_bounds__(THREADS)
void rnn_modrelu_kernel(const float* __restrict__ inputs,   // [B, SEQ]
                        const float* __restrict__ W_ih,     // [H, 1]
                        const float* __restrict__ W_hh,     // [H, H]
                        const float* __restrict__ b_mod,    // [H]
                        const float* __restrict__ W_lin,    // [NC, H]
                        const float* __restrict__ b_lin,    // [NC]
                        float* __restrict__ out)            // [B, NC]
{
    __shared__ __align__(16) ull   wsm[H * 16];          // 3840 B
    __shared__ __align__(16) float xs[TCH * THREADS];    // 14336 B
    __shared__ __align__(16) ull   zsc[NDP + 1][THREADS];// 16 KB scratch (z pairs)

    const int tid = threadIdx.x;
    const int b   = blockIdx.x * THREADS + tid;
    const int b0  = blockIdx.x * THREADS;

    // ---- build weight table (once) ----
    for (int idx = tid; idx < H * 16; idx += THREADS) {
        const int d = idx >> 4, k = idx & 15;
        float lo, hi;
        if (k < 15) { lo = W_hh[d * H + 2 * k]; hi = W_hh[d * H + 2 * k + 1]; }
        else        { lo = W_ih[d];             hi = b_mod[d]; }
        wsm[d * 16 + k] = pack2(lo, hi);
    }
    __syncthreads();

    ull hp[NDP];
#pragma unroll
    for (int q = 0; q < NDP; q++) hp[q] = 0ull;

    for (int ch = 0; ch < TCH; ch++) {
        // ---- stage 28 steps of x for all 128 rows ----
        for (int idx = tid; idx < TCH * THREADS; idx += THREADS) {
            const int r = idx / TCH;
            const int i = idx - r * TCH;
            xs[i * THREADS + r] = inputs[(size_t)(b0 + r) * SEQ + ch * TCH + i];
        }
        __syncthreads();

#pragma unroll 1
        for (int i = 0; i < TCH; i++) {
            const float x = xs[i * THREADS + tid];

            // ---- matvec: one dim-pair per loop iteration (NOT unrolled) ----
#pragma unroll 1
            for (int p = 0; p < NDP; p++) {
                const ulonglong2* r0 = (const ulonglong2*)(wsm + (2 * p) * 16);
                const ulonglong2* r1 = (const ulonglong2*)(wsm + (2 * p + 1) * 16);

                ull a = 0ull, c = 0ull;
#pragma unroll
                for (int q = 0; q < 7; q++) {
                    const ulonglong2 u0 = r0[q];
                    const ulonglong2 u1 = r1[q];
                    a = ffma2(u0.x, hp[2 * q],     a);
                    c = ffma2(u1.x, hp[2 * q],     c);
                    a = ffma2(u0.y, hp[2 * q + 1], a);
                    c = ffma2(u1.y, hp[2 * q + 1], c);
                }
                const ulonglong2 t0 = r0[7];   // (.x = k-pair 14, .y = (wih, b))
                const ulonglong2 t1 = r1[7];
                a = ffma2(t0.x, hp[14], a);
                c = ffma2(t1.x, hp[14], c);

                float al, ah, cl, chh;
                unpack2(a, al, ah);
                unpack2(c, cl, chh);
                float w0, bb0, w1, bb1;
                unpack2(t0.y, w0, bb0);
                unpack2(t1.y, w1, bb1);

                const float z0 = fmaf(x, w0, al + ah);
                const float z1 = fmaf(x, w1, cl + chh);
                zsc[p][tid] = pack2(modrelu(z0, bb0), modrelu(z1, bb1));
            }

            // ---- read back new h (conflict-free, 8x LDS.128) ----
#pragma unroll
            for (int q = 0; q < NDP; q++) hp[q] = zsc[q][tid];
        }
        __syncthreads();   // xs reuse barrier
    }

    // ---- final linear ----
    float h[H];
#pragma unroll
    for (int q = 0; q < NDP; q++) unpack2(hp[q], h[2 * q], h[2 * q + 1]);
#pragma unroll
    for (int c = 0; c < NC; c++) {
        float s = b_lin[c];
#pragma unroll
        for (int k = 0; k < H; k++)
            s = fmaf(W_lin[c * H + k], h[k], s);
        out[(size_t)b * NC + c] = s;
    }
}

extern "C" void kernel_launch(void* const* d_in, const int* in_sizes, int n_in,
                              void* d_out, int out_size) {
    const float* inputs = (const float*)d_in[0];
    const float* W_ih   = (const float*)d_in[1];
    const float* W_hh   = (const float*)d_in[2];
    const float* b_mod  = (const float*)d_in[3];
    const float* W_lin  = (const float*)d_in[4];
    const float* b_lin  = (const float*)d_in[5];
    float* out = (float*)d_out;

    rnn_modrelu_kernel<<<BATCHN / THREADS, THREADS>>>(inputs, W_ih, W_hh, b_mod,
                                                      W_lin, b_lin, out);
}